// round 3
// baseline (speedup 1.0000x reference)
#include <cuda_runtime.h>

// IDGNN restructured (validated in R2):
//   p_i = MLP_{0,i}(x);  u = x + A*p0;  d = p1 - p0
//   Un_i = u*W1e[1,i]; Dt_i = d*W1e[1,i]   (W1e[k] = w1[k]+w1[k+128], z=cat([H,H]))
//   S_t = sum_{n in N(t)} relu(Un0[n] + Dt0[t] + b1[1,0])
//   out[t] = u_t + self_t*d_t + S_t*w2[1,0] + deg_t*b2[1,0]
//            + self_t*( (relu(Un1_t+Dt1_t+b1[1,1])*w2[1,1]+b2[1,1])
//                      -(relu(Un0_t+Dt0_t+b1[1,0])*w2[1,0]+b2[1,0]) )
// R3: neighbor bitmask -> shared index lists (MLP-8 gathers), row-tiled matvecs
// (weight reuse R=4..8), W1eff folded into loads, 3 kernels + 1 memset node.

#define NN 256
#define DD 128

// ---- device scratch (zero-initialized at module load; g_adj re-zeroed per call) ----
__device__ unsigned g_adj[NN * 8];
__device__ float    g_p0[NN * DD];
__device__ float    g_p1[NN * DD];
__device__ float    g_u [NN * DD];
__device__ float    g_d [NN * DD];
__device__ float    g_UD[4][NN * DD];   // 0:Un0  1:Dt0  2:Un1  3:Dt1

// Expand g_adj[row] bitmask into nbr[] (one full warp calls this). Returns count.
__device__ __forceinline__ int build_list(int row, int* nbr) {
    int lane = threadIdx.x & 31;
    unsigned word = (lane < 8) ? g_adj[row * 8 + lane] : 0u;
    int pc  = __popc(word);
    int inc = pc;
#pragma unroll
    for (int off = 1; off < 8; off <<= 1) {
        int v = __shfl_up_sync(0xffffffffu, inc, off);
        if (lane >= off) inc += v;
    }
    int base = inc - pc;
    if (lane < 8) {
        unsigned bits = word; int o = base;
        while (bits) { int b = __ffs(bits) - 1; bits &= bits - 1; nbr[o++] = lane * 32 + b; }
    }
    return __shfl_sync(0xffffffffu, inc, 7);
}

// ---------------------------------------------------------------------------
// K1: blocks [0,16) = edge scatter (adjacency atomicOr);
//     blocks [16,144) = p_i MLPs, R=4 rows/block, W1eff folded. block=128
// ---------------------------------------------------------------------------
__global__ void __launch_bounds__(128)
k_prep(const int* __restrict__ ei32, int E, const float* __restrict__ x,
       const float* __restrict__ w1, const float* __restrict__ b1,
       const float* __restrict__ w2, const float* __restrict__ b2) {
    int c = threadIdx.x;
    if (blockIdx.x < 16) {
        // dtype sniff: int64 node ids (<256) => odd int32 words all zero
        int is64 = __syncthreads_and(ei32[2 * c + 1] == 0);
        for (int e = blockIdx.x * 128 + c; e < E; e += 16 * 128) {
            int a, b;
            if (is64) { a = ei32[2 * e]; b = ei32[2 * (E + e)]; }
            else      { a = ei32[e];     b = ei32[E + e]; }
            a &= 255; b &= 255;
            atomicOr(&g_adj[a * 8 + (b >> 5)], 1u << (b & 31));
            atomicOr(&g_adj[b * 8 + (a >> 5)], 1u << (a & 31));
        }
        return;
    }
    int idx  = blockIdx.x - 16;
    int i    = idx >> 6;            // which pre_nn (0/1)
    int row0 = (idx & 63) * 4;
    __shared__ float Xs[4][DD];
    __shared__ float Hs[4][DD];
#pragma unroll
    for (int r = 0; r < 4; r++) Xs[r][c] = x[(row0 + r) * DD + c];
    __syncthreads();
    const float* W = w1 + i * 32768;          // w1[0,i] : [256,128]
    float acc[4] = {0.f, 0.f, 0.f, 0.f};
#pragma unroll 4
    for (int k = 0; k < DD; k++) {
        float we = W[k * DD + c] + W[(k + 128) * DD + c];
#pragma unroll
        for (int r = 0; r < 4; r++) acc[r] = fmaf(Xs[r][k], we, acc[r]);
    }
    float bb1 = b1[i * DD + c];
#pragma unroll
    for (int r = 0; r < 4; r++) Hs[r][c] = fmaxf(acc[r] + bb1, 0.f);
    __syncthreads();
    const float* W2 = w2 + i * 16384;         // w2[0,i]
    float a2[4] = {0.f, 0.f, 0.f, 0.f};
#pragma unroll 4
    for (int k = 0; k < DD; k++) {
        float wv = W2[k * DD + c];
#pragma unroll
        for (int r = 0; r < 4; r++) a2[r] = fmaf(Hs[r][k], wv, a2[r]);
    }
    float bb2 = b2[i * DD + c];
    float* dst = i ? g_p1 : g_p0;
#pragma unroll
    for (int r = 0; r < 4; r++) dst[(row0 + r) * DD + c] = a2[r] + bb2;
}

// ---------------------------------------------------------------------------
// K2: Un0/Dt0/Un1/Dt1 = {u,d} * W1e[1,i].  grid=(32,4), R=8 rows/block.
// combo: bit0 = (d vs u), bit1 = i. u gathered via shared neighbor lists.
// ---------------------------------------------------------------------------
__global__ void __launch_bounds__(128)
k_ud(const float* __restrict__ x, const float* __restrict__ w1) {
    int combo = blockIdx.y;
    int row0  = blockIdx.x * 8;
    int c     = threadIdx.x;
    int wid   = c >> 5;
    __shared__ float Ss[8][DD];
    __shared__ int   nbr[8][NN];
    __shared__ int   cnts[8];
    if (!(combo & 1)) {
        for (int rr = wid; rr < 8; rr += 4) {
            int cn = build_list(row0 + rr, nbr[rr]);
            if ((c & 31) == 0) cnts[rr] = cn;
        }
    }
    __syncthreads();
#pragma unroll
    for (int rr = 0; rr < 8; rr++) {
        int row = row0 + rr;
        float v;
        if (combo & 1) {
            v = g_p1[row * DD + c] - g_p0[row * DD + c];
            if (combo == 1) g_d[row * DD + c] = v;
        } else {
            float acc = x[row * DD + c];
            int n = cnts[rr];
            for (int j = 0; j < n; j += 8) {
#pragma unroll
                for (int u = 0; u < 8; u++)
                    if (j + u < n) acc += g_p0[nbr[rr][j + u] * DD + c];
            }
            v = acc;
            if (combo == 0) g_u[row * DD + c] = v;
        }
        Ss[rr][c] = v;
    }
    __syncthreads();
    const float* W = w1 + (2 + (combo >> 1)) * 32768;   // w1[1,i]
    float acc[8] = {0.f, 0.f, 0.f, 0.f, 0.f, 0.f, 0.f, 0.f};
#pragma unroll 4
    for (int k = 0; k < DD; k++) {
        float we = W[k * DD + c] + W[(k + 128) * DD + c];
#pragma unroll
        for (int r = 0; r < 8; r++) acc[r] = fmaf(Ss[r][k], we, acc[r]);
    }
#pragma unroll
    for (int r = 0; r < 8; r++) g_UD[combo][(row0 + r) * DD + c] = acc[r];
}

// ---------------------------------------------------------------------------
// K3: neighbor relu-sum + final matvec + rare self correction. grid=128, R=2.
// ---------------------------------------------------------------------------
__global__ void __launch_bounds__(128)
k_out(const float* __restrict__ b1, const float* __restrict__ w2,
      const float* __restrict__ b2, float* __restrict__ out) {
    int t0  = blockIdx.x * 2;
    int c   = threadIdx.x;
    int wid = c >> 5;
    __shared__ int   nbr[2][NN];
    __shared__ int   cnts[2];
    __shared__ float Ssum[2][DD];
    __shared__ float H0s[DD];
    __shared__ float H1s[DD];
    if (wid < 2) {
        int cn = build_list(t0 + wid, nbr[wid]);
        if ((c & 31) == 0) cnts[wid] = cn;
    }
    __syncthreads();
    float b10 = b1[256 + c];                 // b1[1,0]
    int   selfFlag[2];
    int   degv[2];
#pragma unroll
    for (int rr = 0; rr < 2; rr++) {
        int t = t0 + rr;
        float pre = g_UD[1][t * DD + c] + b10;   // Dt0[t] + b1[1,0]
        float acc = 0.f;
        int n = cnts[rr];
        for (int j = 0; j < n; j += 8) {
#pragma unroll
            for (int u = 0; u < 8; u++)
                if (j + u < n)
                    acc += fmaxf(g_UD[0][nbr[rr][j + u] * DD + c] + pre, 0.f);
        }
        Ssum[rr][c] = acc;
        unsigned w  = g_adj[t * 8 + (t >> 5)];
        selfFlag[rr] = (w >> (t & 31)) & 1;
        degv[rr]     = n;
    }
    __syncthreads();
    const float* W20 = w2 + 32768;           // w2[1,0]
    float a2[2] = {0.f, 0.f};
#pragma unroll 4
    for (int k = 0; k < DD; k++) {
        float wv = W20[k * DD + c];
        a2[0] = fmaf(Ssum[0][k], wv, a2[0]);
        a2[1] = fmaf(Ssum[1][k], wv, a2[1]);
    }
    float b20 = b2[256 + c];
#pragma unroll
    for (int rr = 0; rr < 2; rr++) {
        int t = t0 + rr;
        float sf  = (float)selfFlag[rr];
        float res = g_u[t * DD + c] + sf * g_d[t * DD + c]
                  + a2[rr] + (float)degv[rr] * b20;
        if (selfFlag[rr]) {                  // block-uniform, rare (~8/256)
            H0s[c] = fmaxf(g_UD[0][t * DD + c] + g_UD[1][t * DD + c] + b10, 0.f);
            H1s[c] = fmaxf(g_UD[2][t * DD + c] + g_UD[3][t * DD + c] + b1[384 + c], 0.f);
            __syncthreads();
            const float* W21 = w2 + 49152;   // w2[1,1]
            float d0 = 0.f, d1 = 0.f;
#pragma unroll 4
            for (int k = 0; k < DD; k++) {
                d0 = fmaf(H0s[k], W20[k * DD + c], d0);
                d1 = fmaf(H1s[k], W21[k * DD + c], d1);
            }
            res += (d1 + b2[384 + c]) - (d0 + b20);
            __syncthreads();
        }
        out[t * DD + c] = res;
    }
}

extern "C" void kernel_launch(void* const* d_in, const int* in_sizes, int n_in,
                              void* d_out, int out_size) {
    const float* x  = (const float*)d_in[0];
    const float* w1 = (const float*)d_in[1];
    const float* b1 = (const float*)d_in[2];
    const float* w2 = (const float*)d_in[3];
    const float* b2 = (const float*)d_in[4];
    const int*   ei = (const int*)d_in[5];   // dtype sniffed on device
    int E = in_sizes[5] / 2;
    float* out = (float*)d_out;

    void* adjPtr = nullptr;
    cudaGetSymbolAddress(&adjPtr, g_adj);
    cudaMemsetAsync(adjPtr, 0, sizeof(unsigned) * NN * 8);

    k_prep<<<144, 128>>>(ei, E, x, w1, b1, w2, b2);
    k_ud  <<<dim3(32, 4), 128>>>(x, w1);
    k_out <<<128, 128>>>(b1, w2, b2, out);
}

// round 4
// speedup vs baseline: 2.5386x; 2.5386x over previous
#include <cuda_runtime.h>

// IDGNN restructured (math validated in R2, rel_err 1.8e-7):
//   p_i = MLP_{0,i}(x);  u = x + A*p0;  d = p1 - p0
//   Un_i = u*W1e[1,i]; Dt_i = d*W1e[1,i]   (W1e[k] = w1[k]+w1[k+128])
//   S_t = sum_{n in N(t)} relu(Un0[n] + Dt0[t] + b1[1,0])
//   out[t] = u_t + self_t*d_t + S_t*w2[1,0] + deg_t*b2[1,0]
//            + self_t*( (relu(Un1_t+Dt1_t+b1[1,1])*w2[1,1]+b2[1,1])
//                      -(relu(Un0_t+Dt0_t+b1[1,0])*w2[1,0]+b2[1,0]) )
// R4: split-K float4 matvecs (MLP~16), warp-per-row float4 gathers from
// shared neighbor lists, k_out self-restores g_adj (no memset node).

#define NN 256
#define DD 128

// ---- device scratch (zero-init at load; g_adj restored to zero by k_out) ----
__device__ unsigned g_adj[NN * 8];
__device__ __align__(16) float g_W1e[4 * DD * DD];
__device__ __align__(16) float g_p0[NN * DD];
__device__ __align__(16) float g_p1[NN * DD];
__device__ __align__(16) float g_u [NN * DD];
__device__ __align__(16) float g_d [NN * DD];
__device__ __align__(16) float g_UD[4][NN * DD];   // 0:Un0 1:Dt0 2:Un1 3:Dt1

__device__ __forceinline__ float4 f4add(float4 a, float4 b) {
    return make_float4(a.x + b.x, a.y + b.y, a.z + b.z, a.w + b.w);
}
__device__ __forceinline__ float4 f4fma(float s, float4 w, float4 a) {
    return make_float4(fmaf(s, w.x, a.x), fmaf(s, w.y, a.y),
                       fmaf(s, w.z, a.z), fmaf(s, w.w, a.w));
}
__device__ __forceinline__ float4 f4relu(float4 a) {
    return make_float4(fmaxf(a.x, 0.f), fmaxf(a.y, 0.f),
                       fmaxf(a.z, 0.f), fmaxf(a.w, 0.f));
}

// Expand g_adj[row] bitmask into nbr[] (full warp). Returns count.
__device__ __forceinline__ int build_list(int row, int* nbr) {
    int lane = threadIdx.x & 31;
    unsigned word = (lane < 8) ? g_adj[row * 8 + lane] : 0u;
    int pc = __popc(word);
    int inc = pc;
#pragma unroll
    for (int off = 1; off < 8; off <<= 1) {
        int v = __shfl_up_sync(0xffffffffu, inc, off);
        if (lane >= off) inc += v;
    }
    int base = inc - pc;
    if (lane < 8) {
        unsigned bits = word; int o = base;
        while (bits) { int b = __ffs(bits) - 1; bits &= bits - 1; nbr[o++] = lane * 32 + b; }
    }
    return __shfl_sync(0xffffffffu, inc, 7);
}

// ---------------------------------------------------------------------------
// K0: blocks [0,16): edge scatter. blocks [16,144): W1e = w1[:128]+w1[128:].
// ---------------------------------------------------------------------------
__global__ void __launch_bounds__(128)
k_build(const int* __restrict__ ei32, int E, const float4* __restrict__ w14) {
    int tid = threadIdx.x;
    if (blockIdx.x < 16) {
        // dtype sniff: int64 node ids (<256, nonneg) => odd int32 words all zero
        int is64 = __syncthreads_and(ei32[2 * tid + 1] == 0);
        for (int e = blockIdx.x * 128 + tid; e < E; e += 16 * 128) {
            int a, b;
            if (is64) { a = ei32[2 * e]; b = ei32[2 * (E + e)]; }
            else      { a = ei32[e];     b = ei32[E + e]; }
            a &= 255; b &= 255;
            atomicOr(&g_adj[a * 8 + (b >> 5)], 1u << (b & 31));
            atomicOr(&g_adj[b * 8 + (a >> 5)], 1u << (a & 31));
        }
        return;
    }
    int j  = (blockIdx.x - 16) * 128 + tid;   // float4 index in [0,16384)
    int li = j >> 12, rem = j & 4095;
    float4 a = w14[li * 8192 + rem];
    float4 b = w14[li * 8192 + rem + 4096];
    ((float4*)g_W1e)[j] = f4add(a, b);
}

// ---------------------------------------------------------------------------
// K1: p_i = (relu(x*W1e[0,i]+b1[0,i]))*w2[0,i]+b2[0,i].
// grid=(64,2) block=128. 4 rows/block, split-K float4.
// ---------------------------------------------------------------------------
__global__ void __launch_bounds__(128, 1)
k_p(const float4* __restrict__ x4, const float* __restrict__ b1,
    const float4* __restrict__ w24, const float* __restrict__ b2) {
    int i = blockIdx.y, row0 = blockIdx.x * 4;
    int tid = threadIdx.x, lane = tid & 31, w = tid >> 5;
    __shared__ float S[4][DD];
    __shared__ float red[4][4][DD];

    ((float4*)S[w])[lane] = x4[(row0 + w) * 32 + lane];
    __syncthreads();

    const float4* W = (const float4*)g_W1e + i * 4096;   // W1e[0,i]
    float4 acc[4] = {};
#pragma unroll
    for (int kk = 0; kk < 32; kk++) {
        int k = w * 32 + kk;
        float4 wv = W[k * 32 + lane];
#pragma unroll
        for (int r = 0; r < 4; r++) acc[r] = f4fma(S[r][k], wv, acc[r]);
    }
#pragma unroll
    for (int r = 0; r < 4; r++) ((float4*)red[w][r])[lane] = acc[r];
    __syncthreads();

    {
        float b1v = b1[i * DD + tid];
        float h[4];
#pragma unroll
        for (int r = 0; r < 4; r++)
            h[r] = red[0][r][tid] + red[1][r][tid] + red[2][r][tid] + red[3][r][tid] + b1v;
#pragma unroll
        for (int r = 0; r < 4; r++) S[r][tid] = fmaxf(h[r], 0.f);
    }
    __syncthreads();

    const float4* W2 = w24 + i * 4096;                    // w2[0,i]
    float4 a2[4] = {};
#pragma unroll
    for (int kk = 0; kk < 32; kk++) {
        int k = w * 32 + kk;
        float4 wv = W2[k * 32 + lane];
#pragma unroll
        for (int r = 0; r < 4; r++) a2[r] = f4fma(S[r][k], wv, a2[r]);
    }
#pragma unroll
    for (int r = 0; r < 4; r++) ((float4*)red[w][r])[lane] = a2[r];
    __syncthreads();

    float b2v = b2[i * DD + tid];
    float* dst = i ? g_p1 : g_p0;
#pragma unroll
    for (int r = 0; r < 4; r++)
        dst[(row0 + r) * DD + tid] =
            red[0][r][tid] + red[1][r][tid] + red[2][r][tid] + red[3][r][tid] + b2v;
}

// ---------------------------------------------------------------------------
// K2: u = x + gather(p0), d = p1-p0; Un_i = u*W1e[1,i], Dt_i = d*W1e[1,i].
// grid=(64,2) block=128. 4 rows/block; warp-per-row float4 gather.
// ---------------------------------------------------------------------------
__global__ void __launch_bounds__(128, 1)
k_ud(const float4* __restrict__ x4) {
    int i = blockIdx.y, row0 = blockIdx.x * 4;
    int tid = threadIdx.x, lane = tid & 31, w = tid >> 5;
    __shared__ float U[4][DD], D[4][DD];
    __shared__ int   nbr[4][NN];
    __shared__ float red[4][8][DD];   // 16KB

    int row = row0 + w;
    int cn = build_list(row, nbr[w]);

    const float4* p04 = (const float4*)g_p0;
    float4 a0 = x4[row * 32 + lane];
    float4 a1 = {}, a2 = {}, a3 = {};
    int j = 0;
    for (; j + 4 <= cn; j += 4) {
        a0 = f4add(a0, p04[nbr[w][j]     * 32 + lane]);
        a1 = f4add(a1, p04[nbr[w][j + 1] * 32 + lane]);
        a2 = f4add(a2, p04[nbr[w][j + 2] * 32 + lane]);
        a3 = f4add(a3, p04[nbr[w][j + 3] * 32 + lane]);
    }
    for (; j < cn; j++) a0 = f4add(a0, p04[nbr[w][j] * 32 + lane]);
    float4 u = f4add(f4add(a0, a1), f4add(a2, a3));
    ((float4*)U[w])[lane] = u;

    float4 p1v = ((const float4*)g_p1)[row * 32 + lane];
    float4 p0v = p04[row * 32 + lane];
    float4 dv = make_float4(p1v.x - p0v.x, p1v.y - p0v.y, p1v.z - p0v.z, p1v.w - p0v.w);
    ((float4*)D[w])[lane] = dv;
    if (i == 0) {
        ((float4*)g_u)[row * 32 + lane] = u;
        ((float4*)g_d)[row * 32 + lane] = dv;
    }
    __syncthreads();

    const float4* W = (const float4*)g_W1e + (2 + i) * 4096;   // W1e[1,i]
    float4 aU[4] = {}, aD[4] = {};
#pragma unroll
    for (int kk = 0; kk < 32; kk++) {
        int k = w * 32 + kk;
        float4 wv = W[k * 32 + lane];
#pragma unroll
        for (int r = 0; r < 4; r++) {
            aU[r] = f4fma(U[r][k], wv, aU[r]);
            aD[r] = f4fma(D[r][k], wv, aD[r]);
        }
    }
#pragma unroll
    for (int r = 0; r < 4; r++) {
        ((float4*)red[w][r])[lane]     = aU[r];
        ((float4*)red[w][4 + r])[lane] = aD[r];
    }
    __syncthreads();

#pragma unroll
    for (int v = 0; v < 8; v++) {
        float s = red[0][v][tid] + red[1][v][tid] + red[2][v][tid] + red[3][v][tid];
        int r = v & 3, isD = v >> 2;
        g_UD[2 * i + isD][(row0 + r) * DD + tid] = s;
    }
}

// ---------------------------------------------------------------------------
// K3: S_t relu-gather, final matvec, rare self correction, output.
// grid=64 block=128. Restores g_adj rows to zero at the end.
// ---------------------------------------------------------------------------
__global__ void __launch_bounds__(128, 1)
k_out(const float* __restrict__ b1, const float4* __restrict__ w24,
      const float* __restrict__ b2, float* __restrict__ out) {
    int t0 = blockIdx.x * 4;
    int tid = threadIdx.x, lane = tid & 31, w = tid >> 5;
    __shared__ float Ssum[4][DD];
    __shared__ int   nbr[4][NN];
    __shared__ float red[4][4][DD];
    __shared__ int   cnts[4], selfS[4];
    __shared__ float Hs[2][DD];

    int t = t0 + w;
    int cn = build_list(t, nbr[w]);
    if (lane == 0) {
        cnts[w]  = cn;
        selfS[w] = (g_adj[t * 8 + (t >> 5)] >> (t & 31)) & 1;
    }
    const float4* UD0 = (const float4*)g_UD[0];
    float4 pre = f4add(((const float4*)g_UD[1])[t * 32 + lane],
                       ((const float4*)(b1 + 2 * DD))[lane]);
    float4 s0 = {}, s1 = {}, s2 = {}, s3 = {};
    int j = 0;
    for (; j + 4 <= cn; j += 4) {
        s0 = f4add(s0, f4relu(f4add(UD0[nbr[w][j]     * 32 + lane], pre)));
        s1 = f4add(s1, f4relu(f4add(UD0[nbr[w][j + 1] * 32 + lane], pre)));
        s2 = f4add(s2, f4relu(f4add(UD0[nbr[w][j + 2] * 32 + lane], pre)));
        s3 = f4add(s3, f4relu(f4add(UD0[nbr[w][j + 3] * 32 + lane], pre)));
    }
    for (; j < cn; j++) s0 = f4add(s0, f4relu(f4add(UD0[nbr[w][j] * 32 + lane], pre)));
    ((float4*)Ssum[w])[lane] = f4add(f4add(s0, s1), f4add(s2, s3));
    __syncthreads();

    const float4* W20 = w24 + 8192;           // w2[1,0]
    float4 acc[4] = {};
#pragma unroll
    for (int kk = 0; kk < 32; kk++) {
        int k = w * 32 + kk;
        float4 wv = W20[k * 32 + lane];
#pragma unroll
        for (int r = 0; r < 4; r++) acc[r] = f4fma(Ssum[r][k], wv, acc[r]);
    }
#pragma unroll
    for (int r = 0; r < 4; r++) ((float4*)red[w][r])[lane] = acc[r];
    __syncthreads();

    float b20 = b2[2 * DD + tid];
    float b10 = b1[2 * DD + tid];
#pragma unroll
    for (int r = 0; r < 4; r++) {
        int tt = t0 + r;
        float a2 = red[0][r][tid] + red[1][r][tid] + red[2][r][tid] + red[3][r][tid];
        float sf = (float)selfS[r];
        float res = g_u[tt * DD + tid] + sf * g_d[tt * DD + tid]
                  + a2 + (float)cnts[r] * b20;
        if (selfS[r]) {                       // block-uniform, rare
            Hs[0][tid] = fmaxf(g_UD[0][tt * DD + tid] + g_UD[1][tt * DD + tid] + b10, 0.f);
            Hs[1][tid] = fmaxf(g_UD[2][tt * DD + tid] + g_UD[3][tt * DD + tid] + b1[3 * DD + tid], 0.f);
            __syncthreads();
            const float* W20f = (const float*)w24 + 32768;
            const float* W21f = (const float*)w24 + 49152;
            float d0 = 0.f, d1 = 0.f;
#pragma unroll 4
            for (int k = 0; k < DD; k++) {
                d0 = fmaf(Hs[0][k], W20f[k * DD + tid], d0);
                d1 = fmaf(Hs[1][k], W21f[k * DD + tid], d1);
            }
            res += (d1 + b2[3 * DD + tid]) - (d0 + b20);
            __syncthreads();
        }
        out[tt * DD + tid] = res;
    }
    // restore adjacency to zero for the next graph replay
    __syncthreads();
    if (tid < 32) g_adj[t0 * 8 + tid] = 0u;
}

extern "C" void kernel_launch(void* const* d_in, const int* in_sizes, int n_in,
                              void* d_out, int out_size) {
    const float* x  = (const float*)d_in[0];
    const float* w1 = (const float*)d_in[1];
    const float* b1 = (const float*)d_in[2];
    const float* w2 = (const float*)d_in[3];
    const float* b2 = (const float*)d_in[4];
    const int*   ei = (const int*)d_in[5];   // dtype sniffed on device
    int E = in_sizes[5] / 2;
    float* out = (float*)d_out;

    k_build<<<144, 128>>>(ei, E, (const float4*)w1);
    k_p    <<<dim3(64, 2), 128>>>((const float4*)x, b1, (const float4*)w2, b2);
    k_ud   <<<dim3(64, 2), 128>>>((const float4*)x);
    k_out  <<<64, 128>>>(b1, (const float4*)w2, b2, out);
}